// round 3
// baseline (speedup 1.0000x reference)
#include <cuda_runtime.h>
#include <cstdint>

#define Rn 786432      // B*N*P
#define Mn 24576       // B*N
#define Hn 64
#define On 128

// ---------------- scratch (static device globals; no allocation) ----------------
__device__ float g_h0[Rn * Hn];
__device__ float g_h1[Rn * Hn];
__device__ float g_h2[Rn * Hn];
__device__ unsigned char g_m8[Rn];
__device__ unsigned char g_valid[Mn];
__device__ float g_sum[3 * 64];
__device__ float g_sq[3 * 64];
__device__ float g_a[3 * 64];
__device__ float g_b[3 * 64];
__device__ int   g_cnt;
__device__ int   g_mode;   // 0=u8 bool, 1=int32, 2=float32

// packed-pair FMA: acc(f32x2) += {a,a} * w(f32x2)
__device__ __forceinline__ void fma2(float2 &acc, float a, float2 w) {
    float2 a2 = make_float2(a, a);
    asm("fma.rn.f32x2 %0, %1, %2, %0;"
        : "+l"(reinterpret_cast<unsigned long long &>(acc))
        : "l"(reinterpret_cast<unsigned long long &>(a2)),
          "l"(reinterpret_cast<unsigned long long &>(w)));
}

// ---------------- K0: zero accumulators + detect mask dtype ----------------
__global__ void k_init(const unsigned char *__restrict__ mraw) {
    int t = threadIdx.x;
    for (int i = t; i < 192; i += 1024) { g_sum[i] = 0.f; g_sq[i] = 0.f; }
    if (t == 0) g_cnt = 0;
    __shared__ int fNB, fMis;
    if (t == 0) { fNB = 0; fMis = 0; }
    __syncthreads();
    // scan first 4096 bytes (buffer is >= 786432 bytes for any candidate dtype)
    uchar4 v = reinterpret_cast<const uchar4 *>(mraw)[t];
    int nb  = (v.x > 1) | (v.y > 1) | (v.z > 1) | (v.w > 1);
    int mis = (v.y != 0) | (v.z != 0) | (v.w != 0);
    if (nb) atomicOr(&fNB, 1);
    if (mis) atomicOr(&fMis, 1);
    __syncthreads();
    if (t == 0) g_mode = fNB ? 2 : (fMis ? 0 : 1);
}

// ---------------- K1: pack mask, valid flags, count ----------------
__global__ void __launch_bounds__(256) k_pack(const void *__restrict__ mraw) {
    int w = blockIdx.x * 8 + (threadIdx.x >> 5);   // polyline id
    int lane = threadIdx.x & 31;
    int r = w * 32 + lane;
    int mode = g_mode;
    int bit;
    if (mode == 0)      bit = reinterpret_cast<const unsigned char *>(mraw)[r] != 0;
    else if (mode == 1) bit = reinterpret_cast<const int *>(mraw)[r] != 0;
    else                bit = reinterpret_cast<const float *>(mraw)[r] != 0.f;
    g_m8[r] = (unsigned char)bit;
    unsigned bal = __ballot_sync(0xffffffffu, bit);
    if (lane == 0) {
        g_valid[w] = bal ? 1 : 0;
        atomicAdd(&g_cnt, __popc(bal));
    }
}

// ---------------- K2: pre GEMM (C=9 -> H=64) + BN0 stats ----------------
__global__ void __launch_bounds__(256) k_pre(const float *__restrict__ x,
                                             const float *__restrict__ Wp) {
    __shared__ float xs[128 * 9];
    __shared__ float wp[576];
    __shared__ float msx[128];
    __shared__ float red[512];
    int t = threadIdx.x;
    int r0 = blockIdx.x * 128;
    for (int i = t; i < 1152; i += 256) xs[i] = x[(size_t)r0 * 9 + i];
    for (int i = t; i < 576; i += 256) wp[i] = Wp[i];
    if (t < 128) msx[t] = (float)g_m8[r0 + t];
    __syncthreads();
    int j = t & 63, g = t >> 6;
    float s = 0.f, ss = 0.f;
    for (int lr = g * 32; lr < g * 32 + 32; lr++) {
        float h = 0.f;
#pragma unroll
        for (int c = 0; c < 9; c++) h = fmaf(xs[lr * 9 + c], wp[j * 9 + c], h);
        g_h0[((size_t)(r0 + lr)) * 64 + j] = h;
        float m = msx[lr];
        s = fmaf(m, h, s);
        ss = fmaf(m * h, h, ss);
    }
    red[j * 4 + g] = s;
    red[256 + j * 4 + g] = ss;
    __syncthreads();
    if (t < 64) {
        float S  = red[t * 4] + red[t * 4 + 1] + red[t * 4 + 2] + red[t * 4 + 3];
        float SS = red[256 + t * 4] + red[256 + t * 4 + 1] + red[256 + t * 4 + 2] + red[256 + t * 4 + 3];
        atomicAdd(&g_sum[t], S);
        atomicAdd(&g_sq[t], SS);
    }
}

// ---------------- finalize BN stage s -> fused a,b ----------------
__global__ void k_finalize(int s, const float *__restrict__ gamma,
                           const float *__restrict__ beta) {
    int j = threadIdx.x;
    float cnt = (float)g_cnt;
    float mean = g_sum[s * 64 + j] / cnt;
    float var = g_sq[s * 64 + j] / cnt - mean * mean;
    var = fmaxf(var, 0.f);
    float inv = rsqrtf(var + 1e-5f);
    float a = gamma[j] * inv;
    g_a[s * 64 + j] = a;
    g_b[s * 64 + j] = beta[j] - mean * a;
}

// ---------------- K4/K6: BN-apply + (pool/concat) + GEMM 64xK + stats ----------------
// layer==1: hin=g_h0 -> hout=g_h1, W=[64][128] (pool path).  layer==2: g_h1->g_h2, W=[64][64].
__global__ void __launch_bounds__(256) k_mlp_layer(const float *__restrict__ W, int layer) {
    extern __shared__ float sm[];
    float *As = sm;                  // [4][32][68]
    float *Wa = sm + 8704;           // [64][68]
    float *Wb = Wa + 4352;           // [64][68]
    float *pooledS = Wb + 4352;      // [4][64]
    float *pcS = pooledS + 256;      // [4][64]
    float *ms = pcS + 256;           // [128]
    float *aS = ms + 128;            // [64]
    float *bS = aS + 64;             // [64]

    const bool pool = (layer == 1);
    const float *hin = pool ? g_h0 : g_h1;
    float *hout = pool ? g_h1 : g_h2;
    const int ain = pool ? 0 : 1;    // BN params from previous stage
    const int sout = pool ? 1 : 2;   // stats accumulation target

    int t = threadIdx.x;
    int r0 = blockIdx.x * 128;

    if (t < 128) ms[t] = (float)g_m8[r0 + t];
    if (t < 64) { aS[t] = g_a[ain * 64 + t]; bS[t] = g_b[ain * 64 + t]; }
    __syncthreads();

    // fill A tile (BN + ReLU + mask), padded stride 68
    const float4 *hin4 = reinterpret_cast<const float4 *>(hin + (size_t)r0 * 64);
    for (int i4 = t; i4 < 2048; i4 += 256) {
        float4 v = hin4[i4];
        int row = i4 >> 4;
        int kq = (i4 & 15) << 2;
        float m = ms[row];
        v.x = fmaxf(fmaf(v.x, aS[kq + 0], bS[kq + 0]), 0.f) * m;
        v.y = fmaxf(fmaf(v.y, aS[kq + 1], bS[kq + 1]), 0.f) * m;
        v.z = fmaxf(fmaf(v.z, aS[kq + 2], bS[kq + 2]), 0.f) * m;
        v.w = fmaxf(fmaf(v.w, aS[kq + 3], bS[kq + 3]), 0.f) * m;
        *reinterpret_cast<float4 *>(&As[(size_t)row * 68 + kq]) = v;
    }
    // load W transposed into smem: Wa[k][h] (= W[h][k]), Wb[k][h] (= W[h][64+k])
    if (pool) {
        for (int idx = t; idx < 8192; idx += 256) {
            float v = W[idx];
            int h = idx >> 7, k2 = idx & 127;
            if (k2 < 64) Wa[k2 * 68 + h] = v;
            else Wb[(k2 - 64) * 68 + h] = v;
        }
    } else {
        for (int idx = t; idx < 4096; idx += 256) {
            float v = W[idx];
            int h = idx >> 6, k2 = idx & 63;
            Wa[k2 * 68 + h] = v;
        }
    }
    __syncthreads();

    if (pool) {
        // maxpool over P (values are >=0; invalid rows are exact zeros, matching ref)
        {
            int q = t >> 6, k = t & 63;
            float mx = 0.f;
            for (int p = 0; p < 32; p++) mx = fmaxf(mx, As[(q * 32 + p) * 68 + k]);
            pooledS[q * 64 + k] = mx;
        }
        __syncthreads();
        // pooled contribution: pc[q][h] = sum_k pooled[q][k] * W[h][64+k]
        {
            int q = t >> 6, h = t & 63;
            float acc = 0.f;
            for (int k = 0; k < 64; k++) acc = fmaf(pooledS[q * 64 + k], Wb[k * 68 + h], acc);
            pcS[q * 64 + h] = acc;
        }
        __syncthreads();
    }

    // GEMM: per thread -> 4 polylines x 8 channels
    int p = t & 31;
    int hg = t >> 5;
    int h0 = hg << 3;
    float2 acc[4][4];
#pragma unroll
    for (int q = 0; q < 4; q++)
#pragma unroll
        for (int j = 0; j < 4; j++) acc[q][j] = make_float2(0.f, 0.f);

    for (int k = 0; k < 64; k += 4) {
        float av[4][4];
#pragma unroll
        for (int q = 0; q < 4; q++) {
            float4 tmp = *reinterpret_cast<const float4 *>(&As[(q * 32 + p) * 68 + k]);
            av[q][0] = tmp.x; av[q][1] = tmp.y; av[q][2] = tmp.z; av[q][3] = tmp.w;
        }
#pragma unroll
        for (int kk = 0; kk < 4; kk++) {
            const float *wr = &Wa[(k + kk) * 68 + h0];
            float4 wlo = *reinterpret_cast<const float4 *>(wr);
            float4 whi = *reinterpret_cast<const float4 *>(wr + 4);
            float2 w0 = make_float2(wlo.x, wlo.y);
            float2 w1 = make_float2(wlo.z, wlo.w);
            float2 w2 = make_float2(whi.x, whi.y);
            float2 w3 = make_float2(whi.z, whi.w);
#pragma unroll
            for (int q = 0; q < 4; q++) {
                float a = av[q][kk];
                fma2(acc[q][0], a, w0);
                fma2(acc[q][1], a, w1);
                fma2(acc[q][2], a, w2);
                fma2(acc[q][3], a, w3);
            }
        }
    }

    // epilogue: add pooled contribution, store, accumulate BN stats
    float vfin[4][8];
#pragma unroll
    for (int q = 0; q < 4; q++) {
#pragma unroll
        for (int j = 0; j < 4; j++) {
            float addlo = pool ? pcS[q * 64 + h0 + 2 * j] : 0.f;
            float addhi = pool ? pcS[q * 64 + h0 + 2 * j + 1] : 0.f;
            vfin[q][2 * j] = acc[q][j].x + addlo;
            vfin[q][2 * j + 1] = acc[q][j].y + addhi;
        }
        size_t base = ((size_t)(r0 + q * 32 + p)) * 64 + h0;
        *reinterpret_cast<float4 *>(&hout[base]) =
            make_float4(vfin[q][0], vfin[q][1], vfin[q][2], vfin[q][3]);
        *reinterpret_cast<float4 *>(&hout[base + 4]) =
            make_float4(vfin[q][4], vfin[q][5], vfin[q][6], vfin[q][7]);
    }
    float mq[4];
#pragma unroll
    for (int q = 0; q < 4; q++) mq[q] = ms[q * 32 + p];
#pragma unroll
    for (int i = 0; i < 8; i++) {
        float s = 0.f, ss = 0.f;
#pragma unroll
        for (int q = 0; q < 4; q++) {
            float v = vfin[q][i];
            s = fmaf(mq[q], v, s);
            ss = fmaf(mq[q] * v, v, ss);
        }
#pragma unroll
        for (int off = 16; off > 0; off >>= 1) {
            s += __shfl_xor_sync(0xffffffffu, s, off);
            ss += __shfl_xor_sync(0xffffffffu, ss, off);
        }
        if (p == 0) {
            atomicAdd(&g_sum[sout * 64 + h0 + i], s);
            atomicAdd(&g_sq[sout * 64 + h0 + i], ss);
        }
    }
}

// ---------------- K8: BN2+ReLU+mask, pool, out-MLP, valid mask ----------------
__global__ void __launch_bounds__(256) k_out(const float *__restrict__ Wo1,
                                             const float *__restrict__ bo1,
                                             const float *__restrict__ Wo2,
                                             const float *__restrict__ bo2,
                                             float *__restrict__ out) {
    __shared__ float As[4 * 32 * 64];
    __shared__ float outS[4 * 64];
    __shared__ float y1S[4 * 64];
    __shared__ float ms[128];
    __shared__ float aS[64], bS[64];
    int t = threadIdx.x;
    int bn0 = blockIdx.x * 4;
    size_t r0 = (size_t)bn0 * 32;

    if (t < 128) ms[t] = (float)g_m8[r0 + t];
    if (t < 64) { aS[t] = g_a[128 + t]; bS[t] = g_b[128 + t]; }
    __syncthreads();
    const float4 *h4 = reinterpret_cast<const float4 *>(g_h2 + r0 * 64);
    for (int i4 = t; i4 < 2048; i4 += 256) {
        float4 v = h4[i4];
        int row = i4 >> 4;
        int kq = (i4 & 15) << 2;
        float m = ms[row];
        v.x = fmaxf(fmaf(v.x, aS[kq + 0], bS[kq + 0]), 0.f) * m;
        v.y = fmaxf(fmaf(v.y, aS[kq + 1], bS[kq + 1]), 0.f) * m;
        v.z = fmaxf(fmaf(v.z, aS[kq + 2], bS[kq + 2]), 0.f) * m;
        v.w = fmaxf(fmaf(v.w, aS[kq + 3], bS[kq + 3]), 0.f) * m;
        *reinterpret_cast<float4 *>(&As[row * 64 + kq]) = v;
    }
    __syncthreads();
    {   // maxpool
        int q = t >> 6, k = t & 63;
        float mx = 0.f;
        for (int p = 0; p < 32; p++) mx = fmaxf(mx, As[(q * 32 + p) * 64 + k]);
        outS[q * 64 + k] = mx;
    }
    __syncthreads();
    {   // y1 = relu(out @ Wo1^T + bo1)
        int q = t >> 6, h = t & 63;
        float acc = bo1[h];
        const float4 *wrow = reinterpret_cast<const float4 *>(Wo1 + h * 64);
#pragma unroll
        for (int k4 = 0; k4 < 16; k4++) {
            float4 w = wrow[k4];
            acc = fmaf(outS[q * 64 + 4 * k4 + 0], w.x, acc);
            acc = fmaf(outS[q * 64 + 4 * k4 + 1], w.y, acc);
            acc = fmaf(outS[q * 64 + 4 * k4 + 2], w.z, acc);
            acc = fmaf(outS[q * 64 + 4 * k4 + 3], w.w, acc);
        }
        y1S[q * 64 + h] = fmaxf(acc, 0.f);
    }
    __syncthreads();
    {   // y = (y1 @ Wo2^T + bo2) * valid
        int q = t >> 6, o = t & 63;
        float vf = g_valid[bn0 + q] ? 1.f : 0.f;
        for (int oo = o; oo < 128; oo += 64) {
            float acc = bo2[oo];
            const float4 *wrow = reinterpret_cast<const float4 *>(Wo2 + oo * 64);
#pragma unroll
            for (int k4 = 0; k4 < 16; k4++) {
                float4 w = wrow[k4];
                acc = fmaf(y1S[q * 64 + 4 * k4 + 0], w.x, acc);
                acc = fmaf(y1S[q * 64 + 4 * k4 + 1], w.y, acc);
                acc = fmaf(y1S[q * 64 + 4 * k4 + 2], w.z, acc);
                acc = fmaf(y1S[q * 64 + 4 * k4 + 3], w.w, acc);
            }
            out[(size_t)(bn0 + q) * 128 + oo] = acc * vf;
        }
    }
}

// ---------------- launcher ----------------
extern "C" void kernel_launch(void *const *d_in, const int *in_sizes, int n_in,
                              void *d_out, int out_size) {
    const float *poly = (const float *)d_in[0];
    const void *mask = d_in[1];
    const float *Wpre = (const float *)d_in[2];
    const float *gpre = (const float *)d_in[3];
    const float *bpre = (const float *)d_in[4];
    const float *W1 = (const float *)d_in[5];
    const float *g1 = (const float *)d_in[6];
    const float *b1 = (const float *)d_in[7];
    const float *W2 = (const float *)d_in[8];
    const float *g2 = (const float *)d_in[9];
    const float *b2 = (const float *)d_in[10];
    const float *Wo1 = (const float *)d_in[11];
    const float *bo1 = (const float *)d_in[12];
    const float *Wo2 = (const float *)d_in[13];
    const float *bo2 = (const float *)d_in[14];
    float *out = (float *)d_out;

    cudaFuncSetAttribute(k_mlp_layer, cudaFuncAttributeMaxDynamicSharedMemorySize, 72704);

    k_init<<<1, 1024>>>((const unsigned char *)mask);
    k_pack<<<3072, 256>>>(mask);
    k_pre<<<6144, 256>>>(poly, Wpre);
    k_finalize<<<1, 64>>>(0, gpre, bpre);
    k_mlp_layer<<<6144, 256, 72704>>>(W1, 1);
    k_finalize<<<1, 64>>>(1, g1, b1);
    k_mlp_layer<<<6144, 256, 72704>>>(W2, 2);
    k_finalize<<<1, 64>>>(2, g2, b2);
    k_out<<<6144, 256>>>(Wo1, bo1, Wo2, bo2, out);
}

// round 4
// speedup vs baseline: 1.0288x; 1.0288x over previous
#include <cuda_runtime.h>
#include <cstdint>

#define Rn 786432      // B*N*P
#define Mn 24576       // B*N
#define Hn 64
#define On 128

// ---------------- scratch (static device globals; no allocation) ----------------
__device__ float g_h1[Rn * Hn];
__device__ float g_h2[Rn * Hn];
__device__ unsigned char g_m8[Rn];
__device__ unsigned char g_valid[Mn];
__device__ float g_sum[3 * 64];
__device__ float g_sq[3 * 64];
__device__ float g_a[2 * 64];
__device__ float g_b[2 * 64];
__device__ int   g_cnt;
__device__ int   g_mode;   // 0=u8 bool, 1=int32, 2=float32

// packed-pair FMA: acc(f32x2) += {a,a} * w(f32x2)
__device__ __forceinline__ void fma2(float2 &acc, float a, float2 w) {
    float2 a2 = make_float2(a, a);
    asm("fma.rn.f32x2 %0, %1, %2, %0;"
        : "+l"(reinterpret_cast<unsigned long long &>(acc))
        : "l"(reinterpret_cast<unsigned long long &>(a2)),
          "l"(reinterpret_cast<unsigned long long &>(w)));
}

// ---------------- K0: zero accumulators + detect mask dtype ----------------
__global__ void k_init(const unsigned char *__restrict__ mraw) {
    int t = threadIdx.x;
    if (t < 192) { g_sum[t] = 0.f; g_sq[t] = 0.f; }
    if (t == 0) g_cnt = 0;
    __shared__ int fNB, fMis;
    if (t == 0) { fNB = 0; fMis = 0; }
    __syncthreads();
    // scan first 4096 bytes (buffer >= 786432 bytes for any candidate dtype)
    for (int i = t; i < 1024; i += 256) {
        uchar4 v = reinterpret_cast<const uchar4 *>(mraw)[i];
        if ((v.x > 1) | (v.y > 1) | (v.z > 1) | (v.w > 1)) atomicOr(&fNB, 1);
        if ((v.y != 0) | (v.z != 0) | (v.w != 0)) atomicOr(&fMis, 1);
    }
    __syncthreads();
    if (t == 0) g_mode = fNB ? 2 : (fMis ? 0 : 1);
}

// ---------------- K1: mask pack + pre GEMM (C=9 -> H=64) stats (NO h0 store) ----------------
__global__ void __launch_bounds__(256) k_pre(const float *__restrict__ x,
                                             const float *__restrict__ Wp,
                                             const void *__restrict__ mraw) {
    __shared__ float xs[128 * 9];
    __shared__ float wp[576];
    __shared__ float msx[128];
    __shared__ float red[512];
    __shared__ int cw[4];
    int t = threadIdx.x;
    int r0 = blockIdx.x * 128;

    // pack mask for this block's 128 rows
    int bit = 0;
    if (t < 128) {
        int r = r0 + t;
        int mode = g_mode;
        if (mode == 0)      bit = reinterpret_cast<const unsigned char *>(mraw)[r] != 0;
        else if (mode == 1) bit = reinterpret_cast<const int *>(mraw)[r] != 0;
        else                bit = reinterpret_cast<const float *>(mraw)[r] != 0.f;
        g_m8[r] = (unsigned char)bit;
        msx[t] = (float)bit;
    }
    unsigned bal = __ballot_sync(0xffffffffu, bit);
    if (t < 128 && (t & 31) == 0) {
        g_valid[blockIdx.x * 4 + (t >> 5)] = bal ? 1 : 0;
        cw[t >> 5] = __popc(bal);
    }
    for (int i = t; i < 1152; i += 256) xs[i] = x[(size_t)r0 * 9 + i];
    for (int i = t; i < 576; i += 256) wp[i] = Wp[i];
    __syncthreads();
    if (t == 0) atomicAdd(&g_cnt, cw[0] + cw[1] + cw[2] + cw[3]);

    int j = t & 63, g = t >> 6;
    float s = 0.f, ss = 0.f;
    for (int lr = g * 32; lr < g * 32 + 32; lr++) {
        float h = 0.f;
#pragma unroll
        for (int c = 0; c < 9; c++) h = fmaf(xs[lr * 9 + c], wp[j * 9 + c], h);
        float m = msx[lr];
        s = fmaf(m, h, s);
        ss = fmaf(m * h, h, ss);
    }
    red[j * 4 + g] = s;
    red[256 + j * 4 + g] = ss;
    __syncthreads();
    if (t < 64) {
        float S  = red[t * 4] + red[t * 4 + 1] + red[t * 4 + 2] + red[t * 4 + 3];
        float SS = red[256 + t * 4] + red[256 + t * 4 + 1] + red[256 + t * 4 + 2] + red[256 + t * 4 + 3];
        atomicAdd(&g_sum[t], S);
        atomicAdd(&g_sq[t], SS);
    }
}

// ---------------- finalize BN stage s (0 or 1) -> fused a,b ----------------
__global__ void k_finalize(int s, const float *__restrict__ gamma,
                           const float *__restrict__ beta) {
    int j = threadIdx.x;
    float cnt = (float)g_cnt;
    float mean = g_sum[s * 64 + j] / cnt;
    float var = g_sq[s * 64 + j] / cnt - mean * mean;
    var = fmaxf(var, 0.f);
    float inv = rsqrtf(var + 1e-5f);
    float a = gamma[j] * inv;
    g_a[s * 64 + j] = a;
    g_b[s * 64 + j] = beta[j] - mean * a;
}

// ---------------- K3: layer1: recompute h0, BN0+ReLU+mask, pool, concat-GEMM, stats ----------------
__global__ void __launch_bounds__(256) k_mlp1(const float *__restrict__ x,
                                              const float *__restrict__ Wp,
                                              const float *__restrict__ W) {
    extern __shared__ float sm[];
    float *As = sm;                  // [4][32][68] = 8704
    float *Wa = sm + 8704;           // [64][68] = 4352 (aliased by xs/wp in stage0)
    float *Wb = Wa + 4352;           // [64][68] = 4352
    float *pooledS = Wb + 4352;      // 256
    float *pcS = pooledS + 256;      // 256
    float *ms = pcS + 256;           // 128
    float *aS = ms + 128;            // 64
    float *bS = aS + 64;             // 64
    float *xs = Wa;                  // 1152 (alias)
    float *wp = Wa + 1152;           // 576  (alias)

    int t = threadIdx.x;
    int r0 = blockIdx.x * 128;

    if (t < 128) ms[t] = (float)g_m8[r0 + t];
    if (t < 64) { aS[t] = g_a[t]; bS[t] = g_b[t]; }
    for (int i = t; i < 1152; i += 256) xs[i] = x[(size_t)r0 * 9 + i];
    for (int i = t; i < 576; i += 256) wp[i] = Wp[i];
    __syncthreads();

    // recompute pre-layer, apply BN0+ReLU+mask directly into As (stride 68)
    {
        int j = t & 63, g = t >> 6;
        float a = aS[j], b = bS[j];
        for (int lr = g * 32; lr < g * 32 + 32; lr++) {
            float h = 0.f;
#pragma unroll
            for (int c = 0; c < 9; c++) h = fmaf(xs[lr * 9 + c], wp[j * 9 + c], h);
            As[lr * 68 + j] = fmaxf(fmaf(h, a, b), 0.f) * ms[lr];
        }
    }
    __syncthreads();

    // load W1 transposed (overwrites xs/wp alias region)
    for (int idx = t; idx < 8192; idx += 256) {
        float v = W[idx];
        int h = idx >> 7, k2 = idx & 127;
        if (k2 < 64) Wa[k2 * 68 + h] = v;
        else Wb[(k2 - 64) * 68 + h] = v;
    }
    __syncthreads();

    // maxpool over P (values >=0; invalid rows exact zeros)
    {
        int q = t >> 6, k = t & 63;
        float mx = 0.f;
        for (int p = 0; p < 32; p++) mx = fmaxf(mx, As[(q * 32 + p) * 68 + k]);
        pooledS[q * 64 + k] = mx;
    }
    __syncthreads();
    // pooled contribution: pc[q][h] = sum_k pooled[q][k] * W[h][64+k]
    {
        int q = t >> 6, h = t & 63;
        float acc = 0.f;
        for (int k = 0; k < 64; k++) acc = fmaf(pooledS[q * 64 + k], Wb[k * 68 + h], acc);
        pcS[q * 64 + h] = acc;
    }
    __syncthreads();

    // GEMM: per thread -> 4 polylines x 8 channels
    int p = t & 31;
    int h0 = (t >> 5) << 3;
    float2 acc[4][4];
#pragma unroll
    for (int q = 0; q < 4; q++)
#pragma unroll
        for (int j = 0; j < 4; j++) acc[q][j] = make_float2(0.f, 0.f);

    for (int k = 0; k < 64; k += 4) {
        float av[4][4];
#pragma unroll
        for (int q = 0; q < 4; q++) {
            float4 tmp = *reinterpret_cast<const float4 *>(&As[(q * 32 + p) * 68 + k]);
            av[q][0] = tmp.x; av[q][1] = tmp.y; av[q][2] = tmp.z; av[q][3] = tmp.w;
        }
#pragma unroll
        for (int kk = 0; kk < 4; kk++) {
            const float *wr = &Wa[(k + kk) * 68 + h0];
            float4 wlo = *reinterpret_cast<const float4 *>(wr);
            float4 whi = *reinterpret_cast<const float4 *>(wr + 4);
            float2 w0 = make_float2(wlo.x, wlo.y);
            float2 w1 = make_float2(wlo.z, wlo.w);
            float2 w2 = make_float2(whi.x, whi.y);
            float2 w3 = make_float2(whi.z, whi.w);
#pragma unroll
            for (int q = 0; q < 4; q++) {
                float a = av[q][kk];
                fma2(acc[q][0], a, w0);
                fma2(acc[q][1], a, w1);
                fma2(acc[q][2], a, w2);
                fma2(acc[q][3], a, w3);
            }
        }
    }

    float vfin[4][8];
#pragma unroll
    for (int q = 0; q < 4; q++) {
#pragma unroll
        for (int j = 0; j < 4; j++) {
            vfin[q][2 * j]     = acc[q][j].x + pcS[q * 64 + h0 + 2 * j];
            vfin[q][2 * j + 1] = acc[q][j].y + pcS[q * 64 + h0 + 2 * j + 1];
        }
        size_t base = ((size_t)(r0 + q * 32 + p)) * 64 + h0;
        *reinterpret_cast<float4 *>(&g_h1[base]) =
            make_float4(vfin[q][0], vfin[q][1], vfin[q][2], vfin[q][3]);
        *reinterpret_cast<float4 *>(&g_h1[base + 4]) =
            make_float4(vfin[q][4], vfin[q][5], vfin[q][6], vfin[q][7]);
    }
    float mq[4];
#pragma unroll
    for (int q = 0; q < 4; q++) mq[q] = ms[q * 32 + p];
#pragma unroll
    for (int i = 0; i < 8; i++) {
        float s = 0.f, ss = 0.f;
#pragma unroll
        for (int q = 0; q < 4; q++) {
            float v = vfin[q][i];
            s = fmaf(mq[q], v, s);
            ss = fmaf(mq[q] * v, v, ss);
        }
#pragma unroll
        for (int off = 16; off > 0; off >>= 1) {
            s += __shfl_xor_sync(0xffffffffu, s, off);
            ss += __shfl_xor_sync(0xffffffffu, ss, off);
        }
        if (p == 0) {
            atomicAdd(&g_sum[64 + h0 + i], s);
            atomicAdd(&g_sq[64 + h0 + i], ss);
        }
    }
}

// ---------------- K5: layer2: BN1+ReLU+mask + GEMM 64x64 + stats (slim smem, 4 blk/SM) ----------------
__global__ void __launch_bounds__(256) k_mlp2(const float *__restrict__ W) {
    extern __shared__ float sm[];
    float *As = sm;                  // 8704
    float *Wa = sm + 8704;           // 4352
    float *ms = Wa + 4352;           // 128
    float *aS = ms + 128;            // 64
    float *bS = aS + 64;             // 64   total 13312 floats = 53248 B

    int t = threadIdx.x;
    int r0 = blockIdx.x * 128;

    if (t < 128) ms[t] = (float)g_m8[r0 + t];
    if (t < 64) { aS[t] = g_a[64 + t]; bS[t] = g_b[64 + t]; }
    __syncthreads();

    const float4 *hin4 = reinterpret_cast<const float4 *>(g_h1 + (size_t)r0 * 64);
    for (int i4 = t; i4 < 2048; i4 += 256) {
        float4 v = hin4[i4];
        int row = i4 >> 4;
        int kq = (i4 & 15) << 2;
        float m = ms[row];
        v.x = fmaxf(fmaf(v.x, aS[kq + 0], bS[kq + 0]), 0.f) * m;
        v.y = fmaxf(fmaf(v.y, aS[kq + 1], bS[kq + 1]), 0.f) * m;
        v.z = fmaxf(fmaf(v.z, aS[kq + 2], bS[kq + 2]), 0.f) * m;
        v.w = fmaxf(fmaf(v.w, aS[kq + 3], bS[kq + 3]), 0.f) * m;
        *reinterpret_cast<float4 *>(&As[(size_t)row * 68 + kq]) = v;
    }
    for (int idx = t; idx < 4096; idx += 256) {
        float v = W[idx];
        int h = idx >> 6, k2 = idx & 63;
        Wa[k2 * 68 + h] = v;
    }
    __syncthreads();

    int p = t & 31;
    int h0 = (t >> 5) << 3;
    float2 acc[4][4];
#pragma unroll
    for (int q = 0; q < 4; q++)
#pragma unroll
        for (int j = 0; j < 4; j++) acc[q][j] = make_float2(0.f, 0.f);

    for (int k = 0; k < 64; k += 4) {
        float av[4][4];
#pragma unroll
        for (int q = 0; q < 4; q++) {
            float4 tmp = *reinterpret_cast<const float4 *>(&As[(q * 32 + p) * 68 + k]);
            av[q][0] = tmp.x; av[q][1] = tmp.y; av[q][2] = tmp.z; av[q][3] = tmp.w;
        }
#pragma unroll
        for (int kk = 0; kk < 4; kk++) {
            const float *wr = &Wa[(k + kk) * 68 + h0];
            float4 wlo = *reinterpret_cast<const float4 *>(wr);
            float4 whi = *reinterpret_cast<const float4 *>(wr + 4);
            float2 w0 = make_float2(wlo.x, wlo.y);
            float2 w1 = make_float2(wlo.z, wlo.w);
            float2 w2 = make_float2(whi.x, whi.y);
            float2 w3 = make_float2(whi.z, whi.w);
#pragma unroll
            for (int q = 0; q < 4; q++) {
                float a = av[q][kk];
                fma2(acc[q][0], a, w0);
                fma2(acc[q][1], a, w1);
                fma2(acc[q][2], a, w2);
                fma2(acc[q][3], a, w3);
            }
        }
    }

    float vfin[4][8];
#pragma unroll
    for (int q = 0; q < 4; q++) {
#pragma unroll
        for (int j = 0; j < 4; j++) {
            vfin[q][2 * j]     = acc[q][j].x;
            vfin[q][2 * j + 1] = acc[q][j].y;
        }
        size_t base = ((size_t)(r0 + q * 32 + p)) * 64 + h0;
        *reinterpret_cast<float4 *>(&g_h2[base]) =
            make_float4(vfin[q][0], vfin[q][1], vfin[q][2], vfin[q][3]);
        *reinterpret_cast<float4 *>(&g_h2[base + 4]) =
            make_float4(vfin[q][4], vfin[q][5], vfin[q][6], vfin[q][7]);
    }
    float mq[4];
#pragma unroll
    for (int q = 0; q < 4; q++) mq[q] = ms[q * 32 + p];
#pragma unroll
    for (int i = 0; i < 8; i++) {
        float s = 0.f, ss = 0.f;
#pragma unroll
        for (int q = 0; q < 4; q++) {
            float v = vfin[q][i];
            s = fmaf(mq[q], v, s);
            ss = fmaf(mq[q] * v, v, ss);
        }
#pragma unroll
        for (int off = 16; off > 0; off >>= 1) {
            s += __shfl_xor_sync(0xffffffffu, s, off);
            ss += __shfl_xor_sync(0xffffffffu, ss, off);
        }
        if (p == 0) {
            atomicAdd(&g_sum[128 + h0 + i], s);
            atomicAdd(&g_sq[128 + h0 + i], ss);
        }
    }
}

// ---------------- K6: fused finalize2 + BN2+ReLU+mask pool + out-MLP ----------------
__global__ void __launch_bounds__(256) k_out(const float *__restrict__ g2,
                                             const float *__restrict__ b2v,
                                             const float *__restrict__ Wo1,
                                             const float *__restrict__ bo1,
                                             const float *__restrict__ Wo2,
                                             const float *__restrict__ bo2,
                                             float *__restrict__ out) {
    __shared__ float outS[256];
    __shared__ float y1S[256];
    __shared__ float ms[128];
    __shared__ float aS[64], bS[64];
    int t = threadIdx.x;
    int bn0 = blockIdx.x * 4;
    size_t r0 = (size_t)bn0 * 32;

    if (t < 128) ms[t] = (float)g_m8[r0 + t];
    if (t < 64) {
        float cnt = (float)g_cnt;
        float mean = g_sum[128 + t] / cnt;
        float var = fmaxf(g_sq[128 + t] / cnt - mean * mean, 0.f);
        float inv = rsqrtf(var + 1e-5f);
        float a = g2[t] * inv;
        aS[t] = a;
        bS[t] = b2v[t] - mean * a;
    }
    __syncthreads();

    int q = t >> 6, k = t & 63;
    {   // pool directly from gmem with BN2+ReLU+mask applied on the fly
        float a = aS[k], b = bS[k];
        const float *base = g_h2 + (r0 + (size_t)q * 32) * 64 + k;
        float mx = 0.f;
#pragma unroll 8
        for (int p = 0; p < 32; p++) {
            float v = fmaxf(fmaf(base[(size_t)p * 64], a, b), 0.f) * ms[q * 32 + p];
            mx = fmaxf(mx, v);
        }
        outS[q * 64 + k] = mx;
    }
    __syncthreads();
    {   // y1 = relu(out @ Wo1^T + bo1)
        float acc = bo1[k];
        const float4 *wrow = reinterpret_cast<const float4 *>(Wo1 + k * 64);
#pragma unroll
        for (int k4 = 0; k4 < 16; k4++) {
            float4 w = wrow[k4];
            acc = fmaf(outS[q * 64 + 4 * k4 + 0], w.x, acc);
            acc = fmaf(outS[q * 64 + 4 * k4 + 1], w.y, acc);
            acc = fmaf(outS[q * 64 + 4 * k4 + 2], w.z, acc);
            acc = fmaf(outS[q * 64 + 4 * k4 + 3], w.w, acc);
        }
        y1S[q * 64 + k] = fmaxf(acc, 0.f);
    }
    __syncthreads();
    {   // y = (y1 @ Wo2^T + bo2) * valid
        float vf = g_valid[bn0 + q] ? 1.f : 0.f;
        for (int oo = k; oo < 128; oo += 64) {
            float acc = bo2[oo];
            const float4 *wrow = reinterpret_cast<const float4 *>(Wo2 + oo * 64);
#pragma unroll
            for (int k4 = 0; k4 < 16; k4++) {
                float4 w = wrow[k4];
                acc = fmaf(y1S[q * 64 + 4 * k4 + 0], w.x, acc);
                acc = fmaf(y1S[q * 64 + 4 * k4 + 1], w.y, acc);
                acc = fmaf(y1S[q * 64 + 4 * k4 + 2], w.z, acc);
                acc = fmaf(y1S[q * 64 + 4 * k4 + 3], w.w, acc);
            }
            out[(size_t)(bn0 + q) * 128 + oo] = acc * vf;
        }
    }
}

// ---------------- launcher ----------------
extern "C" void kernel_launch(void *const *d_in, const int *in_sizes, int n_in,
                              void *d_out, int out_size) {
    const float *poly = (const float *)d_in[0];
    const void *mask = d_in[1];
    const float *Wpre = (const float *)d_in[2];
    const float *gpre = (const float *)d_in[3];
    const float *bpre = (const float *)d_in[4];
    const float *W1 = (const float *)d_in[5];
    const float *g1 = (const float *)d_in[6];
    const float *b1 = (const float *)d_in[7];
    const float *W2 = (const float *)d_in[8];
    const float *g2 = (const float *)d_in[9];
    const float *b2 = (const float *)d_in[10];
    const float *Wo1 = (const float *)d_in[11];
    const float *bo1 = (const float *)d_in[12];
    const float *Wo2 = (const float *)d_in[13];
    const float *bo2 = (const float *)d_in[14];
    float *out = (float *)d_out;

    cudaFuncSetAttribute(k_mlp1, cudaFuncAttributeMaxDynamicSharedMemorySize, 72704);
    cudaFuncSetAttribute(k_mlp2, cudaFuncAttributeMaxDynamicSharedMemorySize, 53248);

    k_init<<<1, 256>>>((const unsigned char *)mask);          // idx 0
    k_pre<<<6144, 256>>>(poly, Wpre, mask);                   // idx 1
    k_finalize<<<1, 64>>>(0, gpre, bpre);                     // idx 2
    k_mlp1<<<6144, 256, 72704>>>(poly, Wpre, W1);             // idx 3
    k_finalize<<<1, 64>>>(1, g1, b1);                         // idx 4
    k_mlp2<<<6144, 256, 53248>>>(W2);                         // idx 5  <- ncu -s 5 lands here
    k_out<<<6144, 256>>>(g2, b2, Wo1, bo1, Wo2, bo2, out);    // idx 6
}